// round 3
// baseline (speedup 1.0000x reference)
#include <cuda_runtime.h>
#include <math.h>

#define B_SZ    8
#define L_SEQ   1024
#define ENC_IN  32
#define D_MODEL 256
#define D_INNER 512
#define D_STATE 16
#define D_CONV  4
#define DT_RANK 16
#define N_LAYERS 2
#define D_FF    1024
#define MROWS   (B_SZ * L_SEQ)   // 8192
#define XDBL_W  (DT_RANK + 2 * D_STATE)   // 48

typedef unsigned long long ull;

// ---------------- scratch (static device globals; no allocs allowed) -------
__device__ float g_h   [MROWS * D_MODEL];
__device__ float g_xz  [MROWS * 2 * D_INNER];
__device__ float g_xc  [MROWS * D_INNER];
__device__ float g_xdbl[MROWS * XDBL_W];
__device__ float g_dt  [MROWS * D_INNER];
__device__ float g_y   [MROWS * D_INNER];
__device__ float g_fc  [B_SZ * D_FF];

// ---------------- packed f32x2 helpers -------------------------------------
__device__ __forceinline__ ull pk2(float x, float y) {
    ull r;
    asm("mov.b64 %0, {%1, %2};" : "=l"(r) : "f"(x), "f"(y));
    return r;
}
__device__ __forceinline__ void fma2(ull& c, ull a, ull b) {
    asm("fma.rn.f32x2 %0, %1, %2, %0;" : "+l"(c) : "l"(a), "l"(b));
}
__device__ __forceinline__ float2 upk2(ull v) {
    float2 r;
    asm("mov.b64 {%0, %1}, %2;" : "=f"(r.x), "=f"(r.y) : "l"(v));
    return r;
}

// ---------------------------------------------------------------------------
// fp32 GEMM, f32x2 FMA, M-paired accumulators, double-buffered smem.
//   C[M,N](ldc=N) = A[M,K](lda) @ W[N,K]^T   (+bias / +softplus)
// epi: 0 none, 1 +bias, 2 softplus(+bias).  TM in {2,4,8}, TN in {4,8}.
// ---------------------------------------------------------------------------
template<int BM, int BN, int BK, int TM, int TN, int TH>
__global__ void __launch_bounds__(TH) gemm_t(
    const float* __restrict__ A, const float* __restrict__ W,
    const float* __restrict__ bias, float* __restrict__ C,
    int N, int K, int lda, int epi)
{
    constexpr int PAD = 4;
    __shared__ float As[2][BK][BM + PAD];
    __shared__ float Ws[2][BK][BN + PAD];
    constexpr int A4 = BM * BK / (TH * 4);
    constexpr int B4 = BN * BK / (TH * 4);
    constexpr int KQ = BK / 4;
    constexpr int TMH = TM / 2;

    const int tid = threadIdx.x;
    const int m0  = blockIdx.x * BM;
    const int n0  = blockIdx.y * BN;
    const int tx  = tid % (BN / TN);
    const int ty  = tid / (BN / TN);

    ull acc[TMH][TN];
#pragma unroll
    for (int i = 0; i < TMH; i++)
#pragma unroll
        for (int j = 0; j < TN; j++) acc[i][j] = 0ull;

    float4 ar[A4], wr[B4];

#define LOADR(K0)                                                             \
    {                                                                         \
        _Pragma("unroll")                                                     \
        for (int t = 0; t < A4; t++) {                                        \
            int idx = tid + t * TH;                                           \
            int row = idx / KQ, kq = idx % KQ;                                \
            ar[t] = *(const float4*)(A + (size_t)(m0 + row) * lda + (K0) + kq * 4); \
        }                                                                     \
        _Pragma("unroll")                                                     \
        for (int t = 0; t < B4; t++) {                                        \
            int idx = tid + t * TH;                                           \
            int row = idx / KQ, kq = idx % KQ;                                \
            int n = n0 + row;                                                 \
            wr[t] = (n < N) ? *(const float4*)(W + (size_t)n * K + (K0) + kq * 4) \
                            : make_float4(0.f, 0.f, 0.f, 0.f);                \
        }                                                                     \
    }

#define STS(S)                                                                \
    {                                                                         \
        _Pragma("unroll")                                                     \
        for (int t = 0; t < A4; t++) {                                        \
            int idx = tid + t * TH;                                           \
            int row = idx / KQ, kq = idx % KQ;                                \
            As[S][kq * 4 + 0][row] = ar[t].x;                                 \
            As[S][kq * 4 + 1][row] = ar[t].y;                                 \
            As[S][kq * 4 + 2][row] = ar[t].z;                                 \
            As[S][kq * 4 + 3][row] = ar[t].w;                                 \
        }                                                                     \
        _Pragma("unroll")                                                     \
        for (int t = 0; t < B4; t++) {                                        \
            int idx = tid + t * TH;                                           \
            int row = idx / KQ, kq = idx % KQ;                                \
            Ws[S][kq * 4 + 0][row] = wr[t].x;                                 \
            Ws[S][kq * 4 + 1][row] = wr[t].y;                                 \
            Ws[S][kq * 4 + 2][row] = wr[t].z;                                 \
            Ws[S][kq * 4 + 3][row] = wr[t].w;                                 \
        }                                                                     \
    }

    LOADR(0);
    STS(0);
    __syncthreads();

    int s = 0;
    for (int k0 = 0; k0 < K; k0 += BK) {
        const bool more = (k0 + BK) < K;
        if (more) LOADR(k0 + BK);

#pragma unroll
        for (int k = 0; k < BK; k++) {
            // A operand: TM contiguous floats -> TM/2 packed pairs, no MOVs
            ull a2[TMH];
#pragma unroll
            for (int q = 0; q < TM / 4; q++) {
                ulonglong2 av = *(const ulonglong2*)&As[s][k][ty * TM + q * 4];
                a2[q * 2 + 0] = av.x;
                a2[q * 2 + 1] = av.y;
            }
            if (TM == 2) a2[0] = *(const ull*)&As[s][k][ty * TM];

            float w[TN];
#pragma unroll
            for (int q = 0; q < TN / 4; q++)
                *(float4*)&w[q * 4] = *(const float4*)&Ws[s][k][tx * TN + q * 4];

#pragma unroll
            for (int j = 0; j < TN; j++) {
                const ull w2 = pk2(w[j], w[j]);
#pragma unroll
                for (int i = 0; i < TMH; i++) fma2(acc[i][j], a2[i], w2);
            }
        }

        if (more) STS(s ^ 1);
        __syncthreads();
        s ^= 1;
    }
#undef LOADR
#undef STS

    // ---- epilogue: un-pair, apply bias/act, vector stores -----------------
#pragma unroll
    for (int ip = 0; ip < TMH; ip++) {
        float r0[TN], r1[TN];
#pragma unroll
        for (int j = 0; j < TN; j++) {
            float2 v = upk2(acc[ip][j]);
            r0[j] = v.x; r1[j] = v.y;
        }
        const int m = m0 + ty * TM + ip * 2;
#pragma unroll
        for (int q = 0; q < TN / 4; q++) {
            const int n = n0 + tx * TN + q * 4;
            if (n >= N) continue;
            float4 v0 = *(float4*)&r0[q * 4];
            float4 v1 = *(float4*)&r1[q * 4];
            if (epi >= 1) {
                float4 bv = *(const float4*)&bias[n];
                v0.x += bv.x; v0.y += bv.y; v0.z += bv.z; v0.w += bv.w;
                v1.x += bv.x; v1.y += bv.y; v1.z += bv.z; v1.w += bv.w;
            }
            if (epi == 2) {
                v0.x = (v0.x > 20.f) ? v0.x : log1pf(__expf(v0.x));
                v0.y = (v0.y > 20.f) ? v0.y : log1pf(__expf(v0.y));
                v0.z = (v0.z > 20.f) ? v0.z : log1pf(__expf(v0.z));
                v0.w = (v0.w > 20.f) ? v0.w : log1pf(__expf(v0.w));
                v1.x = (v1.x > 20.f) ? v1.x : log1pf(__expf(v1.x));
                v1.y = (v1.y > 20.f) ? v1.y : log1pf(__expf(v1.y));
                v1.z = (v1.z > 20.f) ? v1.z : log1pf(__expf(v1.z));
                v1.w = (v1.w > 20.f) ? v1.w : log1pf(__expf(v1.w));
            }
            *(float4*)&C[(size_t)m * N + n]       = v0;
            *(float4*)&C[(size_t)(m + 1) * N + n] = v1;
        }
    }
}

// ---------------------------------------------------------------------------
// Fused causal depthwise conv (width 4) + bias + SiLU.
// ---------------------------------------------------------------------------
__global__ void conv_silu_kernel(const float* __restrict__ xz,
                                 const float* __restrict__ cw,
                                 const float* __restrict__ cb,
                                 float* __restrict__ xc)
{
    int idx = blockIdx.x * blockDim.x + threadIdx.x;
    if (idx >= MROWS * D_INNER) return;
    const int d  = idx & (D_INNER - 1);
    const int bl = idx >> 9;
    const int l  = bl & (L_SEQ - 1);

    const float w0 = cw[d * 4 + 0], w1 = cw[d * 4 + 1];
    const float w2 = cw[d * 4 + 2], w3 = cw[d * 4 + 3];
    const float* base = xz + (size_t)bl * (2 * D_INNER) + d;
    const int stride = 2 * D_INNER;

    float acc = cb[d];
    acc = fmaf(base[0], w3, acc);
    if (l >= 1) acc = fmaf(base[-1 * stride], w2, acc);
    if (l >= 2) acc = fmaf(base[-2 * stride], w1, acc);
    if (l >= 3) acc = fmaf(base[-3 * stride], w0, acc);

    xc[idx] = acc / (1.f + __expf(-acc));
}

// ---------------------------------------------------------------------------
// Selective scan, fused with D-skip and z-gate (silu).
// ---------------------------------------------------------------------------
__global__ void __launch_bounds__(256) scan_kernel(
    const float* __restrict__ dtbuf,
    const float* __restrict__ xc,
    const float* __restrict__ xdbl,
    const float* __restrict__ xz,
    const float* __restrict__ A_log,
    const float* __restrict__ Dskip,
    float* __restrict__ y)
{
    const int warp = (blockIdx.x * blockDim.x + threadIdx.x) >> 5;
    const int lane = threadIdx.x & 31;
    const int grp  = lane >> 4;
    const int n    = lane & 15;
    const int ch   = warp * 2 + grp;
    const int b    = ch >> 9;
    const int d    = ch & 511;

    const float A  = -__expf(A_log[d * 16 + n]);
    const float Dv = Dskip[d];

    float h = 0.f;
    const size_t bl = (size_t)b * L_SEQ;
    const float* pdt = dtbuf + bl * D_INNER + d;
    const float* pu  = xc    + bl * D_INNER + d;
    const float* pB  = xdbl  + bl * XDBL_W + DT_RANK + n;
    const float* pz  = xz    + bl * (2 * D_INNER) + D_INNER + d;
    float*       pyo = y     + bl * D_INNER + d;

    for (int l = 0; l < L_SEQ; l++) {
        const float dt = pdt[(size_t)l * D_INNER];
        const float u  = pu [(size_t)l * D_INNER];
        const float Bv = pB [(size_t)l * XDBL_W];
        const float Cv = pB [(size_t)l * XDBL_W + D_STATE];

        const float dA = __expf(dt * A);
        h = fmaf(dA, h, dt * Bv * u);

        float p = h * Cv;
        p += __shfl_xor_sync(0xffffffffu, p, 1);
        p += __shfl_xor_sync(0xffffffffu, p, 2);
        p += __shfl_xor_sync(0xffffffffu, p, 4);
        p += __shfl_xor_sync(0xffffffffu, p, 8);

        if (n == 0) {
            const float z  = pz[(size_t)l * (2 * D_INNER)];
            const float sz = z / (1.f + __expf(-z));
            pyo[(size_t)l * D_INNER] = (p + u * Dv) * sz;
        }
    }
}

// ---------------------------------------------------------------------------
// Head
// ---------------------------------------------------------------------------
__global__ void head1_kernel(const float* __restrict__ h,
                             const float* __restrict__ p1w,
                             const float* __restrict__ p1b,
                             float* __restrict__ fc)
{
    int idx = blockIdx.x * blockDim.x + threadIdx.x;
    if (idx >= B_SZ * D_FF) return;
    const int b = idx / D_FF;
    const int f = idx - b * D_FF;
    const float4* hp = (const float4*)(h + ((size_t)b * L_SEQ + (L_SEQ - 1)) * D_MODEL);
    const float4* wp = (const float4*)(p1w + (size_t)f * D_MODEL);
    float acc = 0.f;
#pragma unroll 8
    for (int k = 0; k < D_MODEL / 4; k++) {
        float4 a = hp[k], w = wp[k];
        acc += a.x * w.x + a.y * w.y + a.z * w.z + a.w * w.w;
    }
    acc += p1b[f];
    fc[idx] = 0.5f * acc * (1.f + erff(acc * 0.70710678118f));
}

__global__ void head2_kernel(const float* __restrict__ fc,
                             const float* __restrict__ p2w,
                             const float* __restrict__ p2b,
                             float* __restrict__ out)
{
    const int b = blockIdx.x;
    const int t = threadIdx.x;
    float acc = 0.f;
    for (int k = t; k < D_FF; k += 256) acc += fc[b * D_FF + k] * p2w[k];
    __shared__ float s[8];
#pragma unroll
    for (int o = 16; o; o >>= 1) acc += __shfl_xor_sync(0xffffffffu, acc, o);
    if ((t & 31) == 0) s[t >> 5] = acc;
    __syncthreads();
    if (t < 8) {
        float v = s[t];
#pragma unroll
        for (int o = 4; o; o >>= 1) v += __shfl_xor_sync(0x000000ffu, v, o);
        if (t == 0) out[b] = v + p2b[0];
    }
}

// ---------------------------------------------------------------------------
extern "C" void kernel_launch(void* const* d_in, const int* in_sizes, int n_in,
                              void* d_out, int out_size)
{
    (void)in_sizes; (void)n_in; (void)out_size;
    const float* x          = (const float*)d_in[0];
    const float* in_w       = (const float*)d_in[1];
    const float* in_b       = (const float*)d_in[2];
    const float* in_proj_w  = (const float*)d_in[3];
    const float* conv_w     = (const float*)d_in[4];
    const float* conv_b     = (const float*)d_in[5];
    const float* x_proj_w   = (const float*)d_in[6];
    const float* dt_w       = (const float*)d_in[7];
    const float* dt_b       = (const float*)d_in[8];
    const float* A_log      = (const float*)d_in[9];
    const float* D_skip     = (const float*)d_in[10];
    const float* out_proj_w = (const float*)d_in[11];
    const float* p1_w       = (const float*)d_in[12];
    const float* p1_b       = (const float*)d_in[13];
    const float* p2_w       = (const float*)d_in[14];
    const float* p2_b       = (const float*)d_in[15];
    float* out = (float*)d_out;

    float *ph, *pxz, *pxc, *pxdbl, *pdt, *py, *pfc;
    cudaGetSymbolAddress((void**)&ph,    g_h);
    cudaGetSymbolAddress((void**)&pxz,   g_xz);
    cudaGetSymbolAddress((void**)&pxc,   g_xc);
    cudaGetSymbolAddress((void**)&pxdbl, g_xdbl);
    cudaGetSymbolAddress((void**)&pdt,   g_dt);
    cudaGetSymbolAddress((void**)&py,    g_y);
    cudaGetSymbolAddress((void**)&pfc,   g_fc);

    // h = x @ in_w^T + in_b   [8192,256], K=32 : 64x64 -> 512 CTAs
    gemm_t<64, 64, 16, 4, 4, 256><<<dim3(MROWS / 64, D_MODEL / 64), 256>>>(
        x, in_w, in_b, ph, D_MODEL, ENC_IN, ENC_IN, 1);

    for (int i = 0; i < N_LAYERS; i++) {
        const float* ipw = in_proj_w  + (size_t)i * 2 * D_INNER * D_MODEL;
        const float* xpw = x_proj_w   + (size_t)i * XDBL_W * D_INNER;
        const float* dtw = dt_w       + (size_t)i * D_INNER * DT_RANK;
        const float* opw = out_proj_w + (size_t)i * D_MODEL * D_INNER;

        // xz = h @ ipw^T   [8192,1024], K=256 : 128x128 -> 512 CTAs
        gemm_t<128, 128, 16, 8, 8, 256><<<dim3(MROWS / 128, (2 * D_INNER) / 128), 256>>>(
            ph, ipw, nullptr, pxz, 2 * D_INNER, D_MODEL, D_MODEL, 0);

        conv_silu_kernel<<<(MROWS * D_INNER) / 256, 256>>>(pxz,
                conv_w + (size_t)i * D_INNER * D_CONV,
                conv_b + (size_t)i * D_INNER, pxc);

        // xdbl = xc @ xpw^T  [8192,48], K=512 : 16x64 -> 512 CTAs
        gemm_t<16, 64, 16, 2, 8, 64><<<dim3(MROWS / 16, 1), 64>>>(
            pxc, xpw, nullptr, pxdbl, XDBL_W, D_INNER, D_INNER, 0);

        // dt = softplus(xdbl[:, :16] @ dtw^T + dt_b)  [8192,512], K=16 -> 1024 CTAs
        gemm_t<64, 64, 16, 4, 4, 256><<<dim3(MROWS / 64, D_INNER / 64), 256>>>(
            pxdbl, dtw, dt_b + (size_t)i * D_INNER, pdt, D_INNER, DT_RANK, XDBL_W, 2);

        // y = gated selective scan
        scan_kernel<<<(B_SZ * D_INNER / 2) * 32 / 256, 256>>>(pdt, pxc, pxdbl, pxz,
                A_log  + (size_t)i * D_INNER * D_STATE,
                D_skip + (size_t)i * D_INNER, py);

        // h = y @ opw^T   [8192,256], K=512 : 64x64 -> 512 CTAs
        gemm_t<64, 64, 16, 4, 4, 256><<<dim3(MROWS / 64, D_MODEL / 64), 256>>>(
            py, opw, nullptr, ph, D_MODEL, D_INNER, D_INNER, 0);
    }

    head1_kernel<<<(B_SZ * D_FF) / 256, 256>>>(ph, p1_w, p1_b, pfc);
    head2_kernel<<<B_SZ, 256>>>(pfc, p2_w, p2_b, out);
}

// round 4
// speedup vs baseline: 1.6065x; 1.6065x over previous
#include <cuda_runtime.h>
#include <math.h>

#define B_SZ    8
#define L_SEQ   1024
#define ENC_IN  32
#define D_MODEL 256
#define D_INNER 512
#define D_STATE 16
#define D_CONV  4
#define DT_RANK 16
#define N_LAYERS 2
#define D_FF    1024
#define MROWS   (B_SZ * L_SEQ)   // 8192
#define XDBL_W  (DT_RANK + 2 * D_STATE)   // 48

typedef unsigned long long ull;

// ---------------- scratch (static device globals; no allocs allowed) -------
__device__ float g_h   [MROWS * D_MODEL];
__device__ float g_xz  [MROWS * 2 * D_INNER];
__device__ float g_xc  [MROWS * D_INNER];
__device__ float g_xdbl[MROWS * XDBL_W];
__device__ float g_dt  [MROWS * D_INNER];
__device__ float g_y   [MROWS * D_INNER];
__device__ float g_fc  [B_SZ * D_FF];

// ---------------- packed f32x2 helpers -------------------------------------
__device__ __forceinline__ ull pk2(float x, float y) {
    ull r;
    asm("mov.b64 %0, {%1, %2};" : "=l"(r) : "f"(x), "f"(y));
    return r;
}
__device__ __forceinline__ void fma2(ull& c, ull a, ull b) {
    asm("fma.rn.f32x2 %0, %1, %2, %0;" : "+l"(c) : "l"(a), "l"(b));
}
__device__ __forceinline__ float2 upk2(ull v) {
    float2 r;
    asm("mov.b64 {%0, %1}, %2;" : "=f"(r.x), "=f"(r.y) : "l"(v));
    return r;
}

// ---------------------------------------------------------------------------
// fp32 GEMM, f32x2 FMA, M-paired accumulators, double-buffered smem.
//   C[M,N](ldc=N) = A[M,K](lda) @ W[N,K]^T   (+bias / +softplus)
// epi: 0 none, 1 +bias, 2 softplus(+bias).  TH = (BM/TM)*(BN/TN).
// ---------------------------------------------------------------------------
template<int BM, int BN, int BK, int TM, int TN, int TH>
__global__ void __launch_bounds__(TH) gemm_t(
    const float* __restrict__ A, const float* __restrict__ W,
    const float* __restrict__ bias, float* __restrict__ C,
    int N, int K, int lda, int epi)
{
    constexpr int PAD = 4;
    __shared__ float As[2][BK][BM + PAD];
    __shared__ float Ws[2][BK][BN + PAD];
    constexpr int A4 = BM * BK / (TH * 4);
    constexpr int B4 = BN * BK / (TH * 4);
    constexpr int KQ = BK / 4;
    constexpr int TMH = TM / 2;

    const int tid = threadIdx.x;
    const int m0  = blockIdx.x * BM;
    const int n0  = blockIdx.y * BN;
    const int tx  = tid % (BN / TN);
    const int ty  = tid / (BN / TN);

    ull acc[TMH][TN];
#pragma unroll
    for (int i = 0; i < TMH; i++)
#pragma unroll
        for (int j = 0; j < TN; j++) acc[i][j] = 0ull;

    float4 ar[A4], wr[B4];

#define LOADR(K0)                                                             \
    {                                                                         \
        _Pragma("unroll")                                                     \
        for (int t = 0; t < A4; t++) {                                        \
            int idx = tid + t * TH;                                           \
            int row = idx / KQ, kq = idx % KQ;                                \
            ar[t] = *(const float4*)(A + (size_t)(m0 + row) * lda + (K0) + kq * 4); \
        }                                                                     \
        _Pragma("unroll")                                                     \
        for (int t = 0; t < B4; t++) {                                        \
            int idx = tid + t * TH;                                           \
            int row = idx / KQ, kq = idx % KQ;                                \
            int n = n0 + row;                                                 \
            wr[t] = (n < N) ? *(const float4*)(W + (size_t)n * K + (K0) + kq * 4) \
                            : make_float4(0.f, 0.f, 0.f, 0.f);                \
        }                                                                     \
    }

#define STS(S)                                                                \
    {                                                                         \
        _Pragma("unroll")                                                     \
        for (int t = 0; t < A4; t++) {                                        \
            int idx = tid + t * TH;                                           \
            int row = idx / KQ, kq = idx % KQ;                                \
            As[S][kq * 4 + 0][row] = ar[t].x;                                 \
            As[S][kq * 4 + 1][row] = ar[t].y;                                 \
            As[S][kq * 4 + 2][row] = ar[t].z;                                 \
            As[S][kq * 4 + 3][row] = ar[t].w;                                 \
        }                                                                     \
        _Pragma("unroll")                                                     \
        for (int t = 0; t < B4; t++) {                                        \
            int idx = tid + t * TH;                                           \
            int row = idx / KQ, kq = idx % KQ;                                \
            Ws[S][kq * 4 + 0][row] = wr[t].x;                                 \
            Ws[S][kq * 4 + 1][row] = wr[t].y;                                 \
            Ws[S][kq * 4 + 2][row] = wr[t].z;                                 \
            Ws[S][kq * 4 + 3][row] = wr[t].w;                                 \
        }                                                                     \
    }

    LOADR(0);
    STS(0);
    __syncthreads();

    int s = 0;
    for (int k0 = 0; k0 < K; k0 += BK) {
        const bool more = (k0 + BK) < K;
        if (more) LOADR(k0 + BK);

#pragma unroll
        for (int k = 0; k < BK; k++) {
            ull a2[TMH];
#pragma unroll
            for (int q = 0; q < TM / 4; q++) {
                ulonglong2 av = *(const ulonglong2*)&As[s][k][ty * TM + q * 4];
                a2[q * 2 + 0] = av.x;
                a2[q * 2 + 1] = av.y;
            }
            if (TM == 2) a2[0] = *(const ull*)&As[s][k][ty * TM];

            float w[TN];
#pragma unroll
            for (int q = 0; q < TN / 4; q++)
                *(float4*)&w[q * 4] = *(const float4*)&Ws[s][k][tx * TN + q * 4];

#pragma unroll
            for (int j = 0; j < TN; j++) {
                const ull w2 = pk2(w[j], w[j]);
#pragma unroll
                for (int i = 0; i < TMH; i++) fma2(acc[i][j], a2[i], w2);
            }
        }

        if (more) STS(s ^ 1);
        __syncthreads();
        s ^= 1;
    }
#undef LOADR
#undef STS

#pragma unroll
    for (int ip = 0; ip < TMH; ip++) {
        float r0[TN], r1[TN];
#pragma unroll
        for (int j = 0; j < TN; j++) {
            float2 v = upk2(acc[ip][j]);
            r0[j] = v.x; r1[j] = v.y;
        }
        const int m = m0 + ty * TM + ip * 2;
#pragma unroll
        for (int q = 0; q < TN / 4; q++) {
            const int n = n0 + tx * TN + q * 4;
            if (n >= N) continue;
            float4 v0 = *(float4*)&r0[q * 4];
            float4 v1 = *(float4*)&r1[q * 4];
            if (epi >= 1) {
                float4 bv = *(const float4*)&bias[n];
                v0.x += bv.x; v0.y += bv.y; v0.z += bv.z; v0.w += bv.w;
                v1.x += bv.x; v1.y += bv.y; v1.z += bv.z; v1.w += bv.w;
            }
            if (epi == 2) {
                v0.x = (v0.x > 20.f) ? v0.x : log1pf(__expf(v0.x));
                v0.y = (v0.y > 20.f) ? v0.y : log1pf(__expf(v0.y));
                v0.z = (v0.z > 20.f) ? v0.z : log1pf(__expf(v0.z));
                v0.w = (v0.w > 20.f) ? v0.w : log1pf(__expf(v0.w));
                v1.x = (v1.x > 20.f) ? v1.x : log1pf(__expf(v1.x));
                v1.y = (v1.y > 20.f) ? v1.y : log1pf(__expf(v1.y));
                v1.z = (v1.z > 20.f) ? v1.z : log1pf(__expf(v1.z));
                v1.w = (v1.w > 20.f) ? v1.w : log1pf(__expf(v1.w));
            }
            *(float4*)&C[(size_t)m * N + n]       = v0;
            *(float4*)&C[(size_t)(m + 1) * N + n] = v1;
        }
    }
}

// ---------------------------------------------------------------------------
// Fused causal depthwise conv (width 4) + bias + SiLU.
// ---------------------------------------------------------------------------
__global__ void conv_silu_kernel(const float* __restrict__ xz,
                                 const float* __restrict__ cw,
                                 const float* __restrict__ cb,
                                 float* __restrict__ xc)
{
    int idx = blockIdx.x * blockDim.x + threadIdx.x;
    if (idx >= MROWS * D_INNER) return;
    const int d  = idx & (D_INNER - 1);
    const int bl = idx >> 9;
    const int l  = bl & (L_SEQ - 1);

    const float w0 = cw[d * 4 + 0], w1 = cw[d * 4 + 1];
    const float w2 = cw[d * 4 + 2], w3 = cw[d * 4 + 3];
    const float* base = xz + (size_t)bl * (2 * D_INNER) + d;
    const int stride = 2 * D_INNER;

    float acc = cb[d];
    acc = fmaf(base[0], w3, acc);
    if (l >= 1) acc = fmaf(base[-1 * stride], w2, acc);
    if (l >= 2) acc = fmaf(base[-2 * stride], w1, acc);
    if (l >= 3) acc = fmaf(base[-3 * stride], w0, acc);

    xc[idx] = acc / (1.f + __expf(-acc));
}

// ---------------------------------------------------------------------------
// Selective scan with depth-2 software-pipelined loads.
// 16 lanes per (b,d) channel; 2 channels/warp; butterfly-reduce y.
// ---------------------------------------------------------------------------
__global__ void __launch_bounds__(256) scan_kernel(
    const float* __restrict__ dtbuf,
    const float* __restrict__ xc,
    const float* __restrict__ xdbl,
    const float* __restrict__ xz,
    const float* __restrict__ A_log,
    const float* __restrict__ Dskip,
    float* __restrict__ y)
{
    const int warp = (blockIdx.x * blockDim.x + threadIdx.x) >> 5;
    const int lane = threadIdx.x & 31;
    const int grp  = lane >> 4;
    const int n    = lane & 15;
    const int ch   = warp * 2 + grp;
    const int b    = ch >> 9;
    const int d    = ch & 511;

    const float A  = -__expf(A_log[d * 16 + n]);
    const float Dv = Dskip[d];

    float h = 0.f;
    const size_t bl = (size_t)b * L_SEQ;
    const float* pdt = dtbuf + bl * D_INNER + d;
    const float* pu  = xc    + bl * D_INNER + d;
    const float* pB  = xdbl  + bl * XDBL_W + DT_RANK + n;
    const float* pz  = xz    + bl * (2 * D_INNER) + D_INNER + d;
    float*       pyo = y     + bl * D_INNER + d;

    // depth-2 pipeline buffers
    float dt_p[2], u_p[2], B_p[2], C_p[2], z_p[2];
#pragma unroll
    for (int q = 0; q < 2; q++) {
        dt_p[q] = pdt[(size_t)q * D_INNER];
        u_p [q] = pu [(size_t)q * D_INNER];
        B_p [q] = pB [(size_t)q * XDBL_W];
        C_p [q] = pB [(size_t)q * XDBL_W + D_STATE];
        z_p [q] = pz [(size_t)q * (2 * D_INNER)];
    }

    for (int l = 0; l < L_SEQ; l++) {
        const int cur = l & 1;
        const float dt = dt_p[cur];
        const float u  = u_p [cur];
        const float Bv = B_p [cur];
        const float Cv = C_p [cur];
        const float z  = z_p [cur];

        // prefetch step l+2 into the slot just freed
        const int ln = (l + 2 < L_SEQ) ? (l + 2) : (L_SEQ - 1);
        dt_p[cur] = pdt[(size_t)ln * D_INNER];
        u_p [cur] = pu [(size_t)ln * D_INNER];
        B_p [cur] = pB [(size_t)ln * XDBL_W];
        C_p [cur] = pB [(size_t)ln * XDBL_W + D_STATE];
        z_p [cur] = pz [(size_t)ln * (2 * D_INNER)];

        const float dA = __expf(dt * A);
        h = fmaf(dA, h, dt * Bv * u);

        float p = h * Cv;
        p += __shfl_xor_sync(0xffffffffu, p, 1);
        p += __shfl_xor_sync(0xffffffffu, p, 2);
        p += __shfl_xor_sync(0xffffffffu, p, 4);
        p += __shfl_xor_sync(0xffffffffu, p, 8);

        if (n == 0) {
            const float sz = z / (1.f + __expf(-z));
            pyo[(size_t)l * D_INNER] = (p + u * Dv) * sz;
        }
    }
}

// ---------------------------------------------------------------------------
// Head
// ---------------------------------------------------------------------------
__global__ void head1_kernel(const float* __restrict__ h,
                             const float* __restrict__ p1w,
                             const float* __restrict__ p1b,
                             float* __restrict__ fc)
{
    int idx = blockIdx.x * blockDim.x + threadIdx.x;
    if (idx >= B_SZ * D_FF) return;
    const int b = idx / D_FF;
    const int f = idx - b * D_FF;
    const float4* hp = (const float4*)(h + ((size_t)b * L_SEQ + (L_SEQ - 1)) * D_MODEL);
    const float4* wp = (const float4*)(p1w + (size_t)f * D_MODEL);
    float acc = 0.f;
#pragma unroll 8
    for (int k = 0; k < D_MODEL / 4; k++) {
        float4 a = hp[k], w = wp[k];
        acc += a.x * w.x + a.y * w.y + a.z * w.z + a.w * w.w;
    }
    acc += p1b[f];
    fc[idx] = 0.5f * acc * (1.f + erff(acc * 0.70710678118f));
}

__global__ void head2_kernel(const float* __restrict__ fc,
                             const float* __restrict__ p2w,
                             const float* __restrict__ p2b,
                             float* __restrict__ out)
{
    const int b = blockIdx.x;
    const int t = threadIdx.x;
    float acc = 0.f;
    for (int k = t; k < D_FF; k += 256) acc += fc[b * D_FF + k] * p2w[k];
    __shared__ float s[8];
#pragma unroll
    for (int o = 16; o; o >>= 1) acc += __shfl_xor_sync(0xffffffffu, acc, o);
    if ((t & 31) == 0) s[t >> 5] = acc;
    __syncthreads();
    if (t < 8) {
        float v = s[t];
#pragma unroll
        for (int o = 4; o; o >>= 1) v += __shfl_xor_sync(0x000000ffu, v, o);
        if (t == 0) out[b] = v + p2b[0];
    }
}

// ---------------------------------------------------------------------------
extern "C" void kernel_launch(void* const* d_in, const int* in_sizes, int n_in,
                              void* d_out, int out_size)
{
    (void)in_sizes; (void)n_in; (void)out_size;
    const float* x          = (const float*)d_in[0];
    const float* in_w       = (const float*)d_in[1];
    const float* in_b       = (const float*)d_in[2];
    const float* in_proj_w  = (const float*)d_in[3];
    const float* conv_w     = (const float*)d_in[4];
    const float* conv_b     = (const float*)d_in[5];
    const float* x_proj_w   = (const float*)d_in[6];
    const float* dt_w       = (const float*)d_in[7];
    const float* dt_b       = (const float*)d_in[8];
    const float* A_log      = (const float*)d_in[9];
    const float* D_skip     = (const float*)d_in[10];
    const float* out_proj_w = (const float*)d_in[11];
    const float* p1_w       = (const float*)d_in[12];
    const float* p1_b       = (const float*)d_in[13];
    const float* p2_w       = (const float*)d_in[14];
    const float* p2_b       = (const float*)d_in[15];
    float* out = (float*)d_out;

    float *ph, *pxz, *pxc, *pxdbl, *pdt, *py, *pfc;
    cudaGetSymbolAddress((void**)&ph,    g_h);
    cudaGetSymbolAddress((void**)&pxz,   g_xz);
    cudaGetSymbolAddress((void**)&pxc,   g_xc);
    cudaGetSymbolAddress((void**)&pxdbl, g_xdbl);
    cudaGetSymbolAddress((void**)&pdt,   g_dt);
    cudaGetSymbolAddress((void**)&py,    g_y);
    cudaGetSymbolAddress((void**)&pfc,   g_fc);

    // h = x @ in_w^T + in_b   [8192,256], K=32 : 64x64x128t -> 512 CTAs
    gemm_t<64, 64, 16, 4, 8, 128><<<dim3(MROWS / 64, D_MODEL / 64), 128>>>(
        x, in_w, in_b, ph, D_MODEL, ENC_IN, ENC_IN, 1);

    for (int i = 0; i < N_LAYERS; i++) {
        const float* ipw = in_proj_w  + (size_t)i * 2 * D_INNER * D_MODEL;
        const float* xpw = x_proj_w   + (size_t)i * XDBL_W * D_INNER;
        const float* dtw = dt_w       + (size_t)i * D_INNER * DT_RANK;
        const float* opw = out_proj_w + (size_t)i * D_MODEL * D_INNER;

        // xz = h @ ipw^T   [8192,1024], K=256 : 64x64x128t -> 2048 CTAs
        gemm_t<64, 64, 16, 4, 8, 128><<<dim3(MROWS / 64, (2 * D_INNER) / 64), 128>>>(
            ph, ipw, nullptr, pxz, 2 * D_INNER, D_MODEL, D_MODEL, 0);

        conv_silu_kernel<<<(MROWS * D_INNER) / 256, 256>>>(pxz,
                conv_w + (size_t)i * D_INNER * D_CONV,
                conv_b + (size_t)i * D_INNER, pxc);

        // xdbl = xc @ xpw^T  [8192,48], K=512 : 32x64x128t -> 256 CTAs
        gemm_t<32, 64, 16, 2, 8, 128><<<dim3(MROWS / 32, 1), 128>>>(
            pxc, xpw, nullptr, pxdbl, XDBL_W, D_INNER, D_INNER, 0);

        // dt = softplus(xdbl[:, :16] @ dtw^T + dt_b)  [8192,512], K=16 -> 1024 CTAs
        gemm_t<64, 64, 16, 4, 8, 128><<<dim3(MROWS / 64, D_INNER / 64), 128>>>(
            pxdbl, dtw, dt_b + (size_t)i * D_INNER, pdt, D_INNER, DT_RANK, XDBL_W, 2);

        // y = gated selective scan
        scan_kernel<<<(B_SZ * D_INNER / 2) * 32 / 256, 256>>>(pdt, pxc, pxdbl, pxz,
                A_log  + (size_t)i * D_INNER * D_STATE,
                D_skip + (size_t)i * D_INNER, py);

        // h = y @ opw^T   [8192,256], K=512 : 64x64x128t -> 512 CTAs
        gemm_t<64, 64, 16, 4, 8, 128><<<dim3(MROWS / 64, D_MODEL / 64), 128>>>(
            py, opw, nullptr, ph, D_MODEL, D_INNER, D_INNER, 0);
    }

    head1_kernel<<<(B_SZ * D_FF) / 256, 256>>>(ph, p1_w, p1_b, pfc);
    head2_kernel<<<B_SZ, 256>>>(pfc, p2_w, p2_b, out);
}

// round 5
// speedup vs baseline: 1.7115x; 1.0654x over previous
#include <cuda_runtime.h>
#include <math.h>

#define B_SZ    8
#define L_SEQ   1024
#define ENC_IN  32
#define D_MODEL 256
#define D_INNER 512
#define D_STATE 16
#define D_CONV  4
#define DT_RANK 16
#define N_LAYERS 2
#define D_FF    1024
#define MROWS   (B_SZ * L_SEQ)   // 8192
#define XDBL_W  (DT_RANK + 2 * D_STATE)   // 48
#define KSPL    4

typedef unsigned long long ull;

// ---------------- scratch (static device globals; no allocs allowed) -------
__device__ float g_h   [MROWS * D_MODEL];
__device__ float g_xz  [MROWS * 2 * D_INNER];
__device__ float g_xc  [MROWS * D_INNER];
__device__ float g_xdbl[MROWS * XDBL_W];
__device__ float g_part[KSPL * MROWS * XDBL_W];
__device__ float g_dt  [MROWS * D_INNER];
__device__ float g_y   [MROWS * D_INNER];
__device__ float g_fc  [B_SZ * D_FF];

// ---------------- packed f32x2 helpers -------------------------------------
__device__ __forceinline__ ull pk2(float x, float y) {
    ull r;
    asm("mov.b64 %0, {%1, %2};" : "=l"(r) : "f"(x), "f"(y));
    return r;
}
__device__ __forceinline__ void fma2(ull& c, ull a, ull b) {
    asm("fma.rn.f32x2 %0, %1, %2, %0;" : "+l"(c) : "l"(a), "l"(b));
}
__device__ __forceinline__ float2 upk2(ull v) {
    float2 r;
    asm("mov.b64 {%0, %1}, %2;" : "=f"(r.x), "=f"(r.y) : "l"(v));
    return r;
}

// ---------------------------------------------------------------------------
// fp32 GEMM, f32x2 FMA paired along N (w-pairs direct from LDS, no packing),
// double-buffered smem.  C[M,N] = A[M,K](lda) @ W[N,K]^T  (+bias/+softplus)
// KSPLIT>1: blockIdx.z selects K-slice, writes partial C + z*M*N.
// epi: 0 none, 1 +bias, 2 softplus(+bias)
// ---------------------------------------------------------------------------
template<int BM, int BN, int BK, int TM, int TN, int TH, int KSPLIT>
__global__ void __launch_bounds__(TH) gemm_t(
    const float* __restrict__ A, const float* __restrict__ W,
    const float* __restrict__ bias, float* __restrict__ C,
    int N, int K, int lda, int epi)
{
    static_assert(TM % 4 == 0 && TN % 4 == 0, "");
    constexpr int PAD = 4;
    __shared__ float As[2][BK][BM + PAD];
    __shared__ float Ws[2][BK][BN + PAD];
    constexpr int A4 = BM * BK / (TH * 4);
    constexpr int B4 = BN * BK / (TH * 4);
    constexpr int KQ = BK / 4;
    constexpr int TNH = TN / 2;

    const int tid = threadIdx.x;
    const int m0  = blockIdx.x * BM;
    const int n0  = blockIdx.y * BN;
    const int tx  = tid % (BN / TN);
    const int ty  = tid / (BN / TN);

    const int klen = K / KSPLIT;
    const int kb   = (KSPLIT > 1) ? blockIdx.z * klen : 0;
    float* Cout = (KSPLIT > 1)
        ? C + (size_t)blockIdx.z * gridDim.x * BM * N
        : C;

    ull acc[TM][TNH];
#pragma unroll
    for (int i = 0; i < TM; i++)
#pragma unroll
        for (int j = 0; j < TNH; j++) acc[i][j] = 0ull;

    float4 ar[A4], wr[B4];

#define LOADR(K0)                                                             \
    {                                                                         \
        _Pragma("unroll")                                                     \
        for (int t = 0; t < A4; t++) {                                        \
            int idx = tid + t * TH;                                           \
            int row = idx / KQ, kq = idx % KQ;                                \
            ar[t] = *(const float4*)(A + (size_t)(m0 + row) * lda + (K0) + kq * 4); \
        }                                                                     \
        _Pragma("unroll")                                                     \
        for (int t = 0; t < B4; t++) {                                        \
            int idx = tid + t * TH;                                           \
            int row = idx / KQ, kq = idx % KQ;                                \
            int n = n0 + row;                                                 \
            wr[t] = (n < N) ? *(const float4*)(W + (size_t)n * K + (K0) + kq * 4) \
                            : make_float4(0.f, 0.f, 0.f, 0.f);                \
        }                                                                     \
    }

#define STS(S)                                                                \
    {                                                                         \
        _Pragma("unroll")                                                     \
        for (int t = 0; t < A4; t++) {                                        \
            int idx = tid + t * TH;                                           \
            int row = idx / KQ, kq = idx % KQ;                                \
            As[S][kq * 4 + 0][row] = ar[t].x;                                 \
            As[S][kq * 4 + 1][row] = ar[t].y;                                 \
            As[S][kq * 4 + 2][row] = ar[t].z;                                 \
            As[S][kq * 4 + 3][row] = ar[t].w;                                 \
        }                                                                     \
        _Pragma("unroll")                                                     \
        for (int t = 0; t < B4; t++) {                                        \
            int idx = tid + t * TH;                                           \
            int row = idx / KQ, kq = idx % KQ;                                \
            Ws[S][kq * 4 + 0][row] = wr[t].x;                                 \
            Ws[S][kq * 4 + 1][row] = wr[t].y;                                 \
            Ws[S][kq * 4 + 2][row] = wr[t].z;                                 \
            Ws[S][kq * 4 + 3][row] = wr[t].w;                                 \
        }                                                                     \
    }

    LOADR(kb);
    STS(0);
    __syncthreads();

    int s = 0;
    for (int k0 = kb; k0 < kb + klen; k0 += BK) {
        const bool more = (k0 + BK) < (kb + klen);
        if (more) LOADR(k0 + BK);

#pragma unroll
        for (int k = 0; k < BK; k++) {
            float a[TM];
#pragma unroll
            for (int q = 0; q < TM / 4; q++)
                *(float4*)&a[q * 4] = *(const float4*)&As[s][k][ty * TM + q * 4];

            ull w2[TNH];
#pragma unroll
            for (int q = 0; q < TN / 4; q++) {
                ulonglong2 wv = *(const ulonglong2*)&Ws[s][k][tx * TN + q * 4];
                w2[q * 2 + 0] = wv.x;
                w2[q * 2 + 1] = wv.y;
            }

#pragma unroll
            for (int i = 0; i < TM; i++) {
                const ull a2 = pk2(a[i], a[i]);
#pragma unroll
                for (int j = 0; j < TNH; j++) fma2(acc[i][j], a2, w2[j]);
            }
        }

        if (more) STS(s ^ 1);
        __syncthreads();
        s ^= 1;
    }
#undef LOADR
#undef STS

    // ---- epilogue: adjacent-N pairs unpack to contiguous floats -----------
#pragma unroll
    for (int i = 0; i < TM; i++) {
        float r[TN];
#pragma unroll
        for (int j = 0; j < TNH; j++) {
            float2 v = upk2(acc[i][j]);
            r[2 * j] = v.x; r[2 * j + 1] = v.y;
        }
        const int m = m0 + ty * TM + i;
#pragma unroll
        for (int q = 0; q < TN / 4; q++) {
            const int n = n0 + tx * TN + q * 4;
            if (n >= N) continue;
            float4 v = *(float4*)&r[q * 4];
            if (epi >= 1) {
                float4 bv = *(const float4*)&bias[n];
                v.x += bv.x; v.y += bv.y; v.z += bv.z; v.w += bv.w;
            }
            if (epi == 2) {
                v.x = (v.x > 20.f) ? v.x : log1pf(__expf(v.x));
                v.y = (v.y > 20.f) ? v.y : log1pf(__expf(v.y));
                v.z = (v.z > 20.f) ? v.z : log1pf(__expf(v.z));
                v.w = (v.w > 20.f) ? v.w : log1pf(__expf(v.w));
            }
            *(float4*)&Cout[(size_t)m * N + n] = v;
        }
    }
}

// ---------------------------------------------------------------------------
// Split-K partial reduce: out[i] = sum_s part[s][i]   (float4 granularity)
// ---------------------------------------------------------------------------
__global__ void reduce_part_kernel(const float* __restrict__ part,
                                   float* __restrict__ out)
{
    const int total4 = MROWS * XDBL_W / 4;
    int idx = blockIdx.x * blockDim.x + threadIdx.x;
    if (idx >= total4) return;
    const float4* p = (const float4*)part;
    float4 v = p[idx];
#pragma unroll
    for (int s = 1; s < KSPL; s++) {
        float4 w = p[idx + (size_t)s * total4];
        v.x += w.x; v.y += w.y; v.z += w.z; v.w += w.w;
    }
    ((float4*)out)[idx] = v;
}

// ---------------------------------------------------------------------------
// Fused causal depthwise conv (width 4) + bias + SiLU.
// ---------------------------------------------------------------------------
__global__ void conv_silu_kernel(const float* __restrict__ xz,
                                 const float* __restrict__ cw,
                                 const float* __restrict__ cb,
                                 float* __restrict__ xc)
{
    int idx = blockIdx.x * blockDim.x + threadIdx.x;
    if (idx >= MROWS * D_INNER) return;
    const int d  = idx & (D_INNER - 1);
    const int bl = idx >> 9;
    const int l  = bl & (L_SEQ - 1);

    const float w0 = cw[d * 4 + 0], w1 = cw[d * 4 + 1];
    const float w2 = cw[d * 4 + 2], w3 = cw[d * 4 + 3];
    const float* base = xz + (size_t)bl * (2 * D_INNER) + d;
    const int stride = 2 * D_INNER;

    float acc = cb[d];
    acc = fmaf(base[0], w3, acc);
    if (l >= 1) acc = fmaf(base[-1 * stride], w2, acc);
    if (l >= 2) acc = fmaf(base[-2 * stride], w1, acc);
    if (l >= 3) acc = fmaf(base[-3 * stride], w0, acc);

    xc[idx] = acc / (1.f + __expf(-acc));
}

// ---------------------------------------------------------------------------
// Selective scan with depth-2 software-pipelined loads.
// ---------------------------------------------------------------------------
__global__ void __launch_bounds__(256) scan_kernel(
    const float* __restrict__ dtbuf,
    const float* __restrict__ xc,
    const float* __restrict__ xdbl,
    const float* __restrict__ xz,
    const float* __restrict__ A_log,
    const float* __restrict__ Dskip,
    float* __restrict__ y)
{
    const int warp = (blockIdx.x * blockDim.x + threadIdx.x) >> 5;
    const int lane = threadIdx.x & 31;
    const int grp  = lane >> 4;
    const int n    = lane & 15;
    const int ch   = warp * 2 + grp;
    const int b    = ch >> 9;
    const int d    = ch & 511;

    const float A  = -__expf(A_log[d * 16 + n]);
    const float Dv = Dskip[d];

    float h = 0.f;
    const size_t bl = (size_t)b * L_SEQ;
    const float* pdt = dtbuf + bl * D_INNER + d;
    const float* pu  = xc    + bl * D_INNER + d;
    const float* pB  = xdbl  + bl * XDBL_W + DT_RANK + n;
    const float* pz  = xz    + bl * (2 * D_INNER) + D_INNER + d;
    float*       pyo = y     + bl * D_INNER + d;

    float dt_p[2], u_p[2], B_p[2], C_p[2], z_p[2];
#pragma unroll
    for (int q = 0; q < 2; q++) {
        dt_p[q] = pdt[(size_t)q * D_INNER];
        u_p [q] = pu [(size_t)q * D_INNER];
        B_p [q] = pB [(size_t)q * XDBL_W];
        C_p [q] = pB [(size_t)q * XDBL_W + D_STATE];
        z_p [q] = pz [(size_t)q * (2 * D_INNER)];
    }

    for (int l = 0; l < L_SEQ; l++) {
        const int cur = l & 1;
        const float dt = dt_p[cur];
        const float u  = u_p [cur];
        const float Bv = B_p [cur];
        const float Cv = C_p [cur];
        const float z  = z_p [cur];

        const int ln = (l + 2 < L_SEQ) ? (l + 2) : (L_SEQ - 1);
        dt_p[cur] = pdt[(size_t)ln * D_INNER];
        u_p [cur] = pu [(size_t)ln * D_INNER];
        B_p [cur] = pB [(size_t)ln * XDBL_W];
        C_p [cur] = pB [(size_t)ln * XDBL_W + D_STATE];
        z_p [cur] = pz [(size_t)ln * (2 * D_INNER)];

        const float dA = __expf(dt * A);
        h = fmaf(dA, h, dt * Bv * u);

        float p = h * Cv;
        p += __shfl_xor_sync(0xffffffffu, p, 1);
        p += __shfl_xor_sync(0xffffffffu, p, 2);
        p += __shfl_xor_sync(0xffffffffu, p, 4);
        p += __shfl_xor_sync(0xffffffffu, p, 8);

        if (n == 0) {
            const float sz = z / (1.f + __expf(-z));
            pyo[(size_t)l * D_INNER] = (p + u * Dv) * sz;
        }
    }
}

// ---------------------------------------------------------------------------
// Head
// ---------------------------------------------------------------------------
__global__ void head1_kernel(const float* __restrict__ h,
                             const float* __restrict__ p1w,
                             const float* __restrict__ p1b,
                             float* __restrict__ fc)
{
    int idx = blockIdx.x * blockDim.x + threadIdx.x;
    if (idx >= B_SZ * D_FF) return;
    const int b = idx / D_FF;
    const int f = idx - b * D_FF;
    const float4* hp = (const float4*)(h + ((size_t)b * L_SEQ + (L_SEQ - 1)) * D_MODEL);
    const float4* wp = (const float4*)(p1w + (size_t)f * D_MODEL);
    float acc = 0.f;
#pragma unroll 8
    for (int k = 0; k < D_MODEL / 4; k++) {
        float4 a = hp[k], w = wp[k];
        acc += a.x * w.x + a.y * w.y + a.z * w.z + a.w * w.w;
    }
    acc += p1b[f];
    fc[idx] = 0.5f * acc * (1.f + erff(acc * 0.70710678118f));
}

__global__ void head2_kernel(const float* __restrict__ fc,
                             const float* __restrict__ p2w,
                             const float* __restrict__ p2b,
                             float* __restrict__ out)
{
    const int b = blockIdx.x;
    const int t = threadIdx.x;
    float acc = 0.f;
    for (int k = t; k < D_FF; k += 256) acc += fc[b * D_FF + k] * p2w[k];
    __shared__ float s[8];
#pragma unroll
    for (int o = 16; o; o >>= 1) acc += __shfl_xor_sync(0xffffffffu, acc, o);
    if ((t & 31) == 0) s[t >> 5] = acc;
    __syncthreads();
    if (t < 8) {
        float v = s[t];
#pragma unroll
        for (int o = 4; o; o >>= 1) v += __shfl_xor_sync(0x000000ffu, v, o);
        if (t == 0) out[b] = v + p2b[0];
    }
}

// ---------------------------------------------------------------------------
extern "C" void kernel_launch(void* const* d_in, const int* in_sizes, int n_in,
                              void* d_out, int out_size)
{
    (void)in_sizes; (void)n_in; (void)out_size;
    const float* x          = (const float*)d_in[0];
    const float* in_w       = (const float*)d_in[1];
    const float* in_b       = (const float*)d_in[2];
    const float* in_proj_w  = (const float*)d_in[3];
    const float* conv_w     = (const float*)d_in[4];
    const float* conv_b     = (const float*)d_in[5];
    const float* x_proj_w   = (const float*)d_in[6];
    const float* dt_w       = (const float*)d_in[7];
    const float* dt_b       = (const float*)d_in[8];
    const float* A_log      = (const float*)d_in[9];
    const float* D_skip     = (const float*)d_in[10];
    const float* out_proj_w = (const float*)d_in[11];
    const float* p1_w       = (const float*)d_in[12];
    const float* p1_b       = (const float*)d_in[13];
    const float* p2_w       = (const float*)d_in[14];
    const float* p2_b       = (const float*)d_in[15];
    float* out = (float*)d_out;

    float *ph, *pxz, *pxc, *pxdbl, *ppart, *pdt, *py, *pfc;
    cudaGetSymbolAddress((void**)&ph,    g_h);
    cudaGetSymbolAddress((void**)&pxz,   g_xz);
    cudaGetSymbolAddress((void**)&pxc,   g_xc);
    cudaGetSymbolAddress((void**)&pxdbl, g_xdbl);
    cudaGetSymbolAddress((void**)&ppart, g_part);
    cudaGetSymbolAddress((void**)&pdt,   g_dt);
    cudaGetSymbolAddress((void**)&py,    g_y);
    cudaGetSymbolAddress((void**)&pfc,   g_fc);

    // h = x @ in_w^T + in_b   [8192,256], K=32 : 32x64 -> 1024 CTAs
    gemm_t<32, 64, 16, 4, 4, 128, 1><<<dim3(MROWS / 32, D_MODEL / 64), 128>>>(
        x, in_w, in_b, ph, D_MODEL, ENC_IN, ENC_IN, 1);

    for (int i = 0; i < N_LAYERS; i++) {
        const float* ipw = in_proj_w  + (size_t)i * 2 * D_INNER * D_MODEL;
        const float* xpw = x_proj_w   + (size_t)i * XDBL_W * D_INNER;
        const float* dtw = dt_w       + (size_t)i * D_INNER * DT_RANK;
        const float* opw = out_proj_w + (size_t)i * D_MODEL * D_INNER;

        // xz = h @ ipw^T   [8192,1024], K=256 : 64x64 -> 2048 CTAs
        gemm_t<64, 64, 16, 4, 8, 128, 1><<<dim3(MROWS / 64, (2 * D_INNER) / 64), 128>>>(
            ph, ipw, nullptr, pxz, 2 * D_INNER, D_MODEL, D_MODEL, 0);

        conv_silu_kernel<<<(MROWS * D_INNER) / 256, 256>>>(pxz,
                conv_w + (size_t)i * D_INNER * D_CONV,
                conv_b + (size_t)i * D_INNER, pxc);

        // xdbl partials: [8192,48], K=512 split 4 : 32x64 -> 1024 CTAs
        gemm_t<32, 64, 16, 4, 4, 128, KSPL><<<dim3(MROWS / 32, 1, KSPL), 128>>>(
            pxc, xpw, nullptr, ppart, XDBL_W, D_INNER, D_INNER, 0);
        reduce_part_kernel<<<(MROWS * XDBL_W / 4 + 255) / 256, 256>>>(ppart, pxdbl);

        // dt = softplus(xdbl[:, :16] @ dtw^T + dt_b) [8192,512], K=16 : 2048 CTAs
        gemm_t<32, 64, 16, 4, 4, 128, 1><<<dim3(MROWS / 32, D_INNER / 64), 128>>>(
            pxdbl, dtw, dt_b + (size_t)i * D_INNER, pdt, D_INNER, DT_RANK, XDBL_W, 2);

        // y = gated selective scan
        scan_kernel<<<(B_SZ * D_INNER / 2) * 32 / 256, 256>>>(pdt, pxc, pxdbl, pxz,
                A_log  + (size_t)i * D_INNER * D_STATE,
                D_skip + (size_t)i * D_INNER, py);

        // h = y @ opw^T   [8192,256], K=512 : 32x64 -> 1024 CTAs
        gemm_t<32, 64, 16, 4, 4, 128, 1><<<dim3(MROWS / 32, D_MODEL / 64), 128>>>(
            py, opw, nullptr, ph, D_MODEL, D_INNER, D_INNER, 0);
    }

    head1_kernel<<<(B_SZ * D_FF) / 256, 256>>>(ph, p1_w, p1_b, pfc);
    head2_kernel<<<B_SZ, 256>>>(pfc, p2_w, p2_b, out);
}

// round 6
// speedup vs baseline: 1.8527x; 1.0825x over previous
#include <cuda_runtime.h>
#include <cuda_bf16.h>
#include <mma.h>
#include <math.h>

using namespace nvcuda;

#define B_SZ    8
#define L_SEQ   1024
#define ENC_IN  32
#define D_MODEL 256
#define D_INNER 512
#define D_STATE 16
#define D_CONV  4
#define DT_RANK 16
#define N_LAYERS 2
#define D_FF    1024
#define MROWS   (B_SZ * L_SEQ)   // 8192
#define XDBL_W  (DT_RANK + 2 * D_STATE)   // 48
#define KSPL    4

typedef unsigned long long ull;

// ---------------- scratch (static device globals; no allocs allowed) -------
__device__ float g_h   [MROWS * D_MODEL];
__device__ float g_xz  [MROWS * 2 * D_INNER];
__device__ float g_xc  [MROWS * D_INNER];
__device__ float g_xdbl[MROWS * XDBL_W];
__device__ float g_part[KSPL * MROWS * XDBL_W];
__device__ float g_dt  [MROWS * D_INNER];
__device__ float g_y   [MROWS * D_INNER];
__device__ float g_fc  [B_SZ * D_FF];

// bf16 hi/lo tripled-K buffers for tensor-core GEMMs
__device__ __nv_bfloat16 g_h3 [MROWS * 3 * D_MODEL];   // A3 for in_proj
__device__ __nv_bfloat16 g_y3 [MROWS * 3 * D_INNER];   // A3 for out_proj
__device__ __nv_bfloat16 g_w3a[2 * D_INNER * 3 * D_MODEL]; // W3 in_proj
__device__ __nv_bfloat16 g_w3b[D_MODEL * 3 * D_INNER];     // W3 out_proj

// ---------------- packed f32x2 helpers -------------------------------------
__device__ __forceinline__ ull pk2(float x, float y) {
    ull r;
    asm("mov.b64 %0, {%1, %2};" : "=l"(r) : "f"(x), "f"(y));
    return r;
}
__device__ __forceinline__ void fma2(ull& c, ull a, ull b) {
    asm("fma.rn.f32x2 %0, %1, %2, %0;" : "+l"(c) : "l"(a), "l"(b));
}
__device__ __forceinline__ float2 upk2(ull v) {
    float2 r;
    asm("mov.b64 {%0, %1}, %2;" : "=f"(r.x), "=f"(r.y) : "l"(v));
    return r;
}

// ---------------------------------------------------------------------------
// hi/lo split, tripled K:  out row r: [hi(0..K) | hi(0..K) | lo(0..K)]  (mode 0)
//                          or        [hi       | lo        | hi      ]  (mode 1)
// A uses mode 0, W uses mode 1 so that sum over 3K = Ah*Wh + Ah*Wl + Al*Wh.
// ---------------------------------------------------------------------------
__global__ void split3_kernel(const float* __restrict__ in,
                              __nv_bfloat16* __restrict__ out,
                              int total, int K, int mode)
{
    int idx = blockIdx.x * blockDim.x + threadIdx.x;
    if (idx >= total) return;
    const float x = in[idx];
    const __nv_bfloat16 hi = __float2bfloat16(x);
    const __nv_bfloat16 lo = __float2bfloat16(x - __bfloat162float(hi));
    const int r = idx / K;
    const int k = idx - r * K;
    __nv_bfloat16* o = out + (size_t)r * 3 * K + k;
    o[0] = hi;
    o[K] = mode ? lo : hi;
    o[2 * K] = mode ? hi : lo;
}

// ---------------------------------------------------------------------------
// Tensor-core GEMM (wmma bf16, fp32 accum):
//   C[M,N] = A3[M,K3] @ W3[N,K3]^T      (no bias)
// CTA: 128x64 tile, 256 threads = 8 warps (4 x 2), warp tile 32x32.
// ---------------------------------------------------------------------------
__global__ void __launch_bounds__(256) wmma_gemm(
    const __nv_bfloat16* __restrict__ A, const __nv_bfloat16* __restrict__ W,
    float* __restrict__ C, int N, int K3)
{
    constexpr int LDS = 24;   // 16 + 8 bf16 padding
    __shared__ alignas(16) __nv_bfloat16 Asm[2][128][LDS];
    __shared__ alignas(16) __nv_bfloat16 Bsm[2][64][LDS];

    const int tid = threadIdx.x;
    const int m0  = blockIdx.x * 128;
    const int n0  = blockIdx.y * 64;
    const int wid = tid >> 5;
    const int wm  = wid & 3;          // 0..3
    const int wn  = wid >> 2;         // 0..1

    const int ar = tid >> 1, ac = (tid & 1) * 8;
    const int br = (tid & 127) >> 1, bc = (tid & 1) * 8;
    const bool bok = tid < 128;

    wmma::fragment<wmma::accumulator, 16, 16, 16, float> acc[2][2];
#pragma unroll
    for (int i = 0; i < 2; i++)
#pragma unroll
        for (int j = 0; j < 2; j++) wmma::fill_fragment(acc[i][j], 0.f);

    uint4 aChunk, bChunk;

#define LOADG(K0)                                                             \
    {                                                                         \
        aChunk = *(const uint4*)(A + (size_t)(m0 + ar) * K3 + (K0) + ac);     \
        if (bok)                                                              \
            bChunk = *(const uint4*)(W + (size_t)(n0 + br) * K3 + (K0) + bc); \
    }
#define STORES(S)                                                             \
    {                                                                         \
        *(uint4*)&Asm[S][ar][ac] = aChunk;                                    \
        if (bok) *(uint4*)&Bsm[S][br][bc] = bChunk;                           \
    }

    LOADG(0);
    STORES(0);
    __syncthreads();

    const int nK = K3 / 16;
    int s = 0;
    for (int kt = 0; kt < nK; kt++) {
        const bool more = (kt + 1) < nK;
        if (more) LOADG((kt + 1) * 16);

        wmma::fragment<wmma::matrix_a, 16, 16, 16, __nv_bfloat16, wmma::row_major> af[2];
        wmma::fragment<wmma::matrix_b, 16, 16, 16, __nv_bfloat16, wmma::col_major> bf_[2];
#pragma unroll
        for (int i = 0; i < 2; i++)
            wmma::load_matrix_sync(af[i], &Asm[s][wm * 32 + i * 16][0], LDS);
#pragma unroll
        for (int j = 0; j < 2; j++)
            wmma::load_matrix_sync(bf_[j], &Bsm[s][wn * 32 + j * 16][0], LDS);
#pragma unroll
        for (int i = 0; i < 2; i++)
#pragma unroll
            for (int j = 0; j < 2; j++)
                wmma::mma_sync(acc[i][j], af[i], bf_[j], acc[i][j]);

        if (more) {
            STORES(s ^ 1);
            __syncthreads();
            s ^= 1;
        }
    }
#undef LOADG
#undef STORES

#pragma unroll
    for (int i = 0; i < 2; i++)
#pragma unroll
        for (int j = 0; j < 2; j++)
            wmma::store_matrix_sync(
                &C[(size_t)(m0 + wm * 32 + i * 16) * N + n0 + wn * 32 + j * 16],
                acc[i][j], N, wmma::mem_row_major);
}

// ---------------------------------------------------------------------------
// fp32 GEMM (FFMA f32x2), used for small-K GEMMs (init, dt) and split-K xdbl.
// ---------------------------------------------------------------------------
template<int BM, int BN, int BK, int TM, int TN, int TH, int KSPLIT>
__global__ void __launch_bounds__(TH) gemm_t(
    const float* __restrict__ A, const float* __restrict__ W,
    const float* __restrict__ bias, float* __restrict__ C,
    int N, int K, int lda, int epi)
{
    static_assert(TM % 4 == 0 && TN % 4 == 0, "");
    constexpr int PAD = 4;
    __shared__ float As[2][BK][BM + PAD];
    __shared__ float Ws[2][BK][BN + PAD];
    constexpr int A4 = BM * BK / (TH * 4);
    constexpr int B4 = BN * BK / (TH * 4);
    constexpr int KQ = BK / 4;
    constexpr int TNH = TN / 2;

    const int tid = threadIdx.x;
    const int m0  = blockIdx.x * BM;
    const int n0  = blockIdx.y * BN;
    const int tx  = tid % (BN / TN);
    const int ty  = tid / (BN / TN);

    const int klen = K / KSPLIT;
    const int kb   = (KSPLIT > 1) ? blockIdx.z * klen : 0;
    float* Cout = (KSPLIT > 1)
        ? C + (size_t)blockIdx.z * gridDim.x * BM * N
        : C;

    ull acc[TM][TNH];
#pragma unroll
    for (int i = 0; i < TM; i++)
#pragma unroll
        for (int j = 0; j < TNH; j++) acc[i][j] = 0ull;

    float4 ar[A4], wr[B4];

#define LOADR(K0)                                                             \
    {                                                                         \
        _Pragma("unroll")                                                     \
        for (int t = 0; t < A4; t++) {                                        \
            int idx = tid + t * TH;                                           \
            int row = idx / KQ, kq = idx % KQ;                                \
            ar[t] = *(const float4*)(A + (size_t)(m0 + row) * lda + (K0) + kq * 4); \
        }                                                                     \
        _Pragma("unroll")                                                     \
        for (int t = 0; t < B4; t++) {                                        \
            int idx = tid + t * TH;                                           \
            int row = idx / KQ, kq = idx % KQ;                                \
            int n = n0 + row;                                                 \
            wr[t] = (n < N) ? *(const float4*)(W + (size_t)n * K + (K0) + kq * 4) \
                            : make_float4(0.f, 0.f, 0.f, 0.f);                \
        }                                                                     \
    }

#define STS(S)                                                                \
    {                                                                         \
        _Pragma("unroll")                                                     \
        for (int t = 0; t < A4; t++) {                                        \
            int idx = tid + t * TH;                                           \
            int row = idx / KQ, kq = idx % KQ;                                \
            As[S][kq * 4 + 0][row] = ar[t].x;                                 \
            As[S][kq * 4 + 1][row] = ar[t].y;                                 \
            As[S][kq * 4 + 2][row] = ar[t].z;                                 \
            As[S][kq * 4 + 3][row] = ar[t].w;                                 \
        }                                                                     \
        _Pragma("unroll")                                                     \
        for (int t = 0; t < B4; t++) {                                        \
            int idx = tid + t * TH;                                           \
            int row = idx / KQ, kq = idx % KQ;                                \
            Ws[S][kq * 4 + 0][row] = wr[t].x;                                 \
            Ws[S][kq * 4 + 1][row] = wr[t].y;                                 \
            Ws[S][kq * 4 + 2][row] = wr[t].z;                                 \
            Ws[S][kq * 4 + 3][row] = wr[t].w;                                 \
        }                                                                     \
    }

    LOADR(kb);
    STS(0);
    __syncthreads();

    int s = 0;
    for (int k0 = kb; k0 < kb + klen; k0 += BK) {
        const bool more = (k0 + BK) < (kb + klen);
        if (more) LOADR(k0 + BK);

#pragma unroll
        for (int k = 0; k < BK; k++) {
            float a[TM];
#pragma unroll
            for (int q = 0; q < TM / 4; q++)
                *(float4*)&a[q * 4] = *(const float4*)&As[s][k][ty * TM + q * 4];

            ull w2[TNH];
#pragma unroll
            for (int q = 0; q < TN / 4; q++) {
                ulonglong2 wv = *(const ulonglong2*)&Ws[s][k][tx * TN + q * 4];
                w2[q * 2 + 0] = wv.x;
                w2[q * 2 + 1] = wv.y;
            }

#pragma unroll
            for (int i = 0; i < TM; i++) {
                const ull a2 = pk2(a[i], a[i]);
#pragma unroll
                for (int j = 0; j < TNH; j++) fma2(acc[i][j], a2, w2[j]);
            }
        }

        if (more) STS(s ^ 1);
        __syncthreads();
        s ^= 1;
    }
#undef LOADR
#undef STS

#pragma unroll
    for (int i = 0; i < TM; i++) {
        float r[TN];
#pragma unroll
        for (int j = 0; j < TNH; j++) {
            float2 v = upk2(acc[i][j]);
            r[2 * j] = v.x; r[2 * j + 1] = v.y;
        }
        const int m = m0 + ty * TM + i;
#pragma unroll
        for (int q = 0; q < TN / 4; q++) {
            const int n = n0 + tx * TN + q * 4;
            if (n >= N) continue;
            float4 v = *(float4*)&r[q * 4];
            if (epi >= 1) {
                float4 bv = *(const float4*)&bias[n];
                v.x += bv.x; v.y += bv.y; v.z += bv.z; v.w += bv.w;
            }
            if (epi == 2) {
                v.x = (v.x > 20.f) ? v.x : log1pf(__expf(v.x));
                v.y = (v.y > 20.f) ? v.y : log1pf(__expf(v.y));
                v.z = (v.z > 20.f) ? v.z : log1pf(__expf(v.z));
                v.w = (v.w > 20.f) ? v.w : log1pf(__expf(v.w));
            }
            *(float4*)&Cout[(size_t)m * N + n] = v;
        }
    }
}

// ---------------------------------------------------------------------------
__global__ void reduce_part_kernel(const float* __restrict__ part,
                                   float* __restrict__ out)
{
    const int total4 = MROWS * XDBL_W / 4;
    int idx = blockIdx.x * blockDim.x + threadIdx.x;
    if (idx >= total4) return;
    const float4* p = (const float4*)part;
    float4 v = p[idx];
#pragma unroll
    for (int s = 1; s < KSPL; s++) {
        float4 w = p[idx + (size_t)s * total4];
        v.x += w.x; v.y += w.y; v.z += w.z; v.w += w.w;
    }
    ((float4*)out)[idx] = v;
}

// ---------------------------------------------------------------------------
__global__ void conv_silu_kernel(const float* __restrict__ xz,
                                 const float* __restrict__ cw,
                                 const float* __restrict__ cb,
                                 float* __restrict__ xc)
{
    int idx = blockIdx.x * blockDim.x + threadIdx.x;
    if (idx >= MROWS * D_INNER) return;
    const int d  = idx & (D_INNER - 1);
    const int bl = idx >> 9;
    const int l  = bl & (L_SEQ - 1);

    const float w0 = cw[d * 4 + 0], w1 = cw[d * 4 + 1];
    const float w2 = cw[d * 4 + 2], w3 = cw[d * 4 + 3];
    const float* base = xz + (size_t)bl * (2 * D_INNER) + d;
    const int stride = 2 * D_INNER;

    float acc = cb[d];
    acc = fmaf(base[0], w3, acc);
    if (l >= 1) acc = fmaf(base[-1 * stride], w2, acc);
    if (l >= 2) acc = fmaf(base[-2 * stride], w1, acc);
    if (l >= 3) acc = fmaf(base[-3 * stride], w0, acc);

    xc[idx] = acc / (1.f + __expf(-acc));
}

// ---------------------------------------------------------------------------
__global__ void __launch_bounds__(256) scan_kernel(
    const float* __restrict__ dtbuf,
    const float* __restrict__ xc,
    const float* __restrict__ xdbl,
    const float* __restrict__ xz,
    const float* __restrict__ A_log,
    const float* __restrict__ Dskip,
    float* __restrict__ y)
{
    const int warp = (blockIdx.x * blockDim.x + threadIdx.x) >> 5;
    const int lane = threadIdx.x & 31;
    const int grp  = lane >> 4;
    const int n    = lane & 15;
    const int ch   = warp * 2 + grp;
    const int b    = ch >> 9;
    const int d    = ch & 511;

    const float A  = -__expf(A_log[d * 16 + n]);
    const float Dv = Dskip[d];

    float h = 0.f;
    const size_t bl = (size_t)b * L_SEQ;
    const float* pdt = dtbuf + bl * D_INNER + d;
    const float* pu  = xc    + bl * D_INNER + d;
    const float* pB  = xdbl  + bl * XDBL_W + DT_RANK + n;
    const float* pz  = xz    + bl * (2 * D_INNER) + D_INNER + d;
    float*       pyo = y     + bl * D_INNER + d;

    float dt_p[2], u_p[2], B_p[2], C_p[2], z_p[2];
#pragma unroll
    for (int q = 0; q < 2; q++) {
        dt_p[q] = pdt[(size_t)q * D_INNER];
        u_p [q] = pu [(size_t)q * D_INNER];
        B_p [q] = pB [(size_t)q * XDBL_W];
        C_p [q] = pB [(size_t)q * XDBL_W + D_STATE];
        z_p [q] = pz [(size_t)q * (2 * D_INNER)];
    }

    for (int l = 0; l < L_SEQ; l++) {
        const int cur = l & 1;
        const float dt = dt_p[cur];
        const float u  = u_p [cur];
        const float Bv = B_p [cur];
        const float Cv = C_p [cur];
        const float z  = z_p [cur];

        const int ln = (l + 2 < L_SEQ) ? (l + 2) : (L_SEQ - 1);
        dt_p[cur] = pdt[(size_t)ln * D_INNER];
        u_p [cur] = pu [(size_t)ln * D_INNER];
        B_p [cur] = pB [(size_t)ln * XDBL_W];
        C_p [cur] = pB [(size_t)ln * XDBL_W + D_STATE];
        z_p [cur] = pz [(size_t)ln * (2 * D_INNER)];

        const float dA = __expf(dt * A);
        h = fmaf(dA, h, dt * Bv * u);

        float p = h * Cv;
        p += __shfl_xor_sync(0xffffffffu, p, 1);
        p += __shfl_xor_sync(0xffffffffu, p, 2);
        p += __shfl_xor_sync(0xffffffffu, p, 4);
        p += __shfl_xor_sync(0xffffffffu, p, 8);

        if (n == 0) {
            const float sz = z / (1.f + __expf(-z));
            pyo[(size_t)l * D_INNER] = (p + u * Dv) * sz;
        }
    }
}

// ---------------------------------------------------------------------------
__global__ void head1_kernel(const float* __restrict__ h,
                             const float* __restrict__ p1w,
                             const float* __restrict__ p1b,
                             float* __restrict__ fc)
{
    int idx = blockIdx.x * blockDim.x + threadIdx.x;
    if (idx >= B_SZ * D_FF) return;
    const int b = idx / D_FF;
    const int f = idx - b * D_FF;
    const float4* hp = (const float4*)(h + ((size_t)b * L_SEQ + (L_SEQ - 1)) * D_MODEL);
    const float4* wp = (const float4*)(p1w + (size_t)f * D_MODEL);
    float acc = 0.f;
#pragma unroll 8
    for (int k = 0; k < D_MODEL / 4; k++) {
        float4 a = hp[k], w = wp[k];
        acc += a.x * w.x + a.y * w.y + a.z * w.z + a.w * w.w;
    }
    acc += p1b[f];
    fc[idx] = 0.5f * acc * (1.f + erff(acc * 0.70710678118f));
}

__global__ void head2_kernel(const float* __restrict__ fc,
                             const float* __restrict__ p2w,
                             const float* __restrict__ p2b,
                             float* __restrict__ out)
{
    const int b = blockIdx.x;
    const int t = threadIdx.x;
    float acc = 0.f;
    for (int k = t; k < D_FF; k += 256) acc += fc[b * D_FF + k] * p2w[k];
    __shared__ float s[8];
#pragma unroll
    for (int o = 16; o; o >>= 1) acc += __shfl_xor_sync(0xffffffffu, acc, o);
    if ((t & 31) == 0) s[t >> 5] = acc;
    __syncthreads();
    if (t < 8) {
        float v = s[t];
#pragma unroll
        for (int o = 4; o; o >>= 1) v += __shfl_xor_sync(0x000000ffu, v, o);
        if (t == 0) out[b] = v + p2b[0];
    }
}

// ---------------------------------------------------------------------------
extern "C" void kernel_launch(void* const* d_in, const int* in_sizes, int n_in,
                              void* d_out, int out_size)
{
    (void)in_sizes; (void)n_in; (void)out_size;
    const float* x          = (const float*)d_in[0];
    const float* in_w       = (const float*)d_in[1];
    const float* in_b       = (const float*)d_in[2];
    const float* in_proj_w  = (const float*)d_in[3];
    const float* conv_w     = (const float*)d_in[4];
    const float* conv_b     = (const float*)d_in[5];
    const float* x_proj_w   = (const float*)d_in[6];
    const float* dt_w       = (const float*)d_in[7];
    const float* dt_b       = (const float*)d_in[8];
    const float* A_log      = (const float*)d_in[9];
    const float* D_skip     = (const float*)d_in[10];
    const float* out_proj_w = (const float*)d_in[11];
    const float* p1_w       = (const float*)d_in[12];
    const float* p1_b       = (const float*)d_in[13];
    const float* p2_w       = (const float*)d_in[14];
    const float* p2_b       = (const float*)d_in[15];
    float* out = (float*)d_out;

    float *ph, *pxz, *pxc, *pxdbl, *ppart, *pdt, *py, *pfc;
    __nv_bfloat16 *ph3, *py3, *pw3a, *pw3b;
    cudaGetSymbolAddress((void**)&ph,    g_h);
    cudaGetSymbolAddress((void**)&pxz,   g_xz);
    cudaGetSymbolAddress((void**)&pxc,   g_xc);
    cudaGetSymbolAddress((void**)&pxdbl, g_xdbl);
    cudaGetSymbolAddress((void**)&ppart, g_part);
    cudaGetSymbolAddress((void**)&pdt,   g_dt);
    cudaGetSymbolAddress((void**)&py,    g_y);
    cudaGetSymbolAddress((void**)&pfc,   g_fc);
    cudaGetSymbolAddress((void**)&ph3,   g_h3);
    cudaGetSymbolAddress((void**)&py3,   g_y3);
    cudaGetSymbolAddress((void**)&pw3a,  g_w3a);
    cudaGetSymbolAddress((void**)&pw3b,  g_w3b);

    // h = x @ in_w^T + in_b   [8192,256], K=32 (FFMA)
    gemm_t<32, 64, 16, 4, 4, 128, 1><<<dim3(MROWS / 32, D_MODEL / 64), 128>>>(
        x, in_w, in_b, ph, D_MODEL, ENC_IN, ENC_IN, 1);

    for (int i = 0; i < N_LAYERS; i++) {
        const float* ipw = in_proj_w  + (size_t)i * 2 * D_INNER * D_MODEL;
        const float* xpw = x_proj_w   + (size_t)i * XDBL_W * D_INNER;
        const float* dtw = dt_w       + (size_t)i * D_INNER * DT_RANK;
        const float* opw = out_proj_w + (size_t)i * D_MODEL * D_INNER;

        // ---- in_proj on tensor cores: xz = h @ ipw^T  [8192,1024] --------
        split3_kernel<<<(MROWS * D_MODEL + 255) / 256, 256>>>(
            ph, ph3, MROWS * D_MODEL, D_MODEL, 0);
        split3_kernel<<<(2 * D_INNER * D_MODEL + 255) / 256, 256>>>(
            ipw, pw3a, 2 * D_INNER * D_MODEL, D_MODEL, 1);
        wmma_gemm<<<dim3(MROWS / 128, (2 * D_INNER) / 64), 256>>>(
            ph3, pw3a, pxz, 2 * D_INNER, 3 * D_MODEL);

        conv_silu_kernel<<<(MROWS * D_INNER) / 256, 256>>>(pxz,
                conv_w + (size_t)i * D_INNER * D_CONV,
                conv_b + (size_t)i * D_INNER, pxc);

        // xdbl partials: [8192,48], K=512 split 4 (FFMA)
        gemm_t<32, 64, 16, 4, 4, 128, KSPL><<<dim3(MROWS / 32, 1, KSPL), 128>>>(
            pxc, xpw, nullptr, ppart, XDBL_W, D_INNER, D_INNER, 0);
        reduce_part_kernel<<<(MROWS * XDBL_W / 4 + 255) / 256, 256>>>(ppart, pxdbl);

        // dt = softplus(xdbl[:, :16] @ dtw^T + dt_b) [8192,512], K=16 (FFMA)
        gemm_t<32, 64, 16, 4, 4, 128, 1><<<dim3(MROWS / 32, D_INNER / 64), 128>>>(
            pxdbl, dtw, dt_b + (size_t)i * D_INNER, pdt, D_INNER, DT_RANK, XDBL_W, 2);

        // y = gated selective scan
        scan_kernel<<<(B_SZ * D_INNER / 2) * 32 / 256, 256>>>(pdt, pxc, pxdbl, pxz,
                A_log  + (size_t)i * D_INNER * D_STATE,
                D_skip + (size_t)i * D_INNER, py);

        // ---- out_proj on tensor cores: h = y @ opw^T  [8192,256] ---------
        split3_kernel<<<(MROWS * D_INNER + 255) / 256, 256>>>(
            py, py3, MROWS * D_INNER, D_INNER, 0);
        split3_kernel<<<(D_MODEL * D_INNER + 255) / 256, 256>>>(
            opw, pw3b, D_MODEL * D_INNER, D_INNER, 1);
        wmma_gemm<<<dim3(MROWS / 128, D_MODEL / 64), 256>>>(
            py3, pw3b, ph, D_MODEL, 3 * D_INNER);
    }

    head1_kernel<<<(B_SZ * D_FF) / 256, 256>>>(ph, p1_w, p1_b, pfc);
    head2_kernel<<<B_SZ, 256>>>(pfc, p2_w, p2_b, out);
}